// round 9
// baseline (speedup 1.0000x reference)
#include <cuda_runtime.h>
#include <cuda_fp16.h>
#include <math.h>
#include <stdint.h>

#define BB 4
#define TT 2048
#define DD 1024
#define EE 8
#define FF 1024
#define NTOK (BB*TT)           // 8192
#define NASG (NTOK*2)          // 16384
#define MAXA (NASG + EE*128)   // 17408
#define MTILES (MAXA/128)      // 136

// ---------------- scratch ----------------
__device__ int   g_counts[EE];
__device__ int   g_cursor[EE];
__device__ int   g_offsets[EE+1];
__device__ int   g_eidx[NASG];
__device__ float g_ew[NASG];
__device__ int   g_token_of[MAXA];
__device__ float g_weight_of[MAXA];
__device__ int   g_flag;

__device__ __half g_xh [(size_t)NTOK*DD];
__device__ __half g_wgh[(size_t)EE*DD*FF];
__device__ __half g_wuh[(size_t)EE*DD*FF];
__device__ __half g_wdh[(size_t)EE*FF*DD];
__device__ __half g_h  [(size_t)MAXA*FF];

// ---------------- PTX helpers ----------------
__device__ __forceinline__ uint32_t s2u(const void* p) {
    uint32_t a;
    asm("{ .reg .u64 t; cvta.to.shared.u64 t, %1; cvt.u32.u64 %0, t; }" : "=r"(a) : "l"(p));
    return a;
}
#define CP16(dst, src) \
    asm volatile("cp.async.cg.shared.global [%0], [%1], 16;" :: "r"(dst), "l"(src) : "memory")
#define CP_COMMIT() asm volatile("cp.async.commit_group;" ::: "memory")
#define CP_WAIT(N)  asm volatile("cp.async.wait_group %0;" :: "n"(N) : "memory")

#define LDSM4(r0, r1, r2, r3, a) \
    asm volatile("ldmatrix.sync.aligned.m8n8.x4.shared.b16 {%0,%1,%2,%3}, [%4];" \
        : "=r"(r0), "=r"(r1), "=r"(r2), "=r"(r3) : "r"(a))
#define LDSM4T(r0, r1, r2, r3, a) \
    asm volatile("ldmatrix.sync.aligned.m8n8.x4.trans.shared.b16 {%0,%1,%2,%3}, [%4];" \
        : "=r"(r0), "=r"(r1), "=r"(r2), "=r"(r3) : "r"(a))

// mma m16n8k16 fp16 in, fp32 acc
#define MMA_F16(d, a, b0, b1) \
    asm volatile("mma.sync.aligned.m16n8k16.row.col.f32.f16.f16.f32 " \
        "{%0,%1,%2,%3}, {%4,%5,%6,%7}, {%8,%9}, {%0,%1,%2,%3};" \
        : "+f"((d)[0]), "+f"((d)[1]), "+f"((d)[2]), "+f"((d)[3]) \
        : "r"((a)[0]), "r"((a)[1]), "r"((a)[2]), "r"((a)[3]), \
          "r"(b0), "r"(b1))

// ---------------- prep: zero out + counters + weight fp16 convert ----------
__global__ void prep_kernel(float* __restrict__ out,
                            const float* __restrict__ wg,
                            const float* __restrict__ wu,
                            const float* __restrict__ wd) {
    int idx = blockIdx.x * blockDim.x + threadIdx.x;     // 0 .. 8M-1
    if (idx < EE) { g_counts[idx] = 0; g_cursor[idx] = 0; }
    if (idx == 0) g_flag = 0;
    if (idx < MAXA) { g_token_of[idx] = -1; g_weight_of[idx] = 0.f; }

    const int OUT4 = NTOK * DD / 4;                      // 2M
    if (idx < OUT4) {
        ((float4*)out)[idx] = make_float4(0.f, 0.f, 0.f, 0.f);
    } else {
        int j = idx - OUT4;                              // 0 .. 6M-1
        int region = j >> 21;
        int off = j & ((1 << 21) - 1);
        const float* src;
        __half* dst;
        switch (region) {
            case 0:  src = wg; dst = g_wgh; break;
            case 1:  src = wu; dst = g_wuh; break;
            default: src = wd; dst = g_wdh; break;
        }
        float4 v = ((const float4*)src)[off];
        __half2 a = __floats2half2_rn(v.x, v.y);
        __half2 b = __floats2half2_rn(v.z, v.w);
        ((__half2*)dst)[2*off]   = a;
        ((__half2*)dst)[2*off+1] = b;
    }
}

// ---------------- router (also emits fp16 x) ----------------
__global__ void router_kernel(const float* __restrict__ x,
                              const float* __restrict__ wr) {
    __shared__ float s_wr[DD * EE];
    int tid = threadIdx.x;
    for (int i = tid; i < DD * EE / 4; i += blockDim.x)
        ((float4*)s_wr)[i] = ((const float4*)wr)[i];
    __syncthreads();

    int warp = tid >> 5, lane = tid & 31;
    int t = blockIdx.x * 8 + warp;
    const float* xr = x + (size_t)t * DD;

    float acc[EE];
#pragma unroll
    for (int e = 0; e < EE; e++) acc[e] = 0.f;
#pragma unroll
    for (int i = 0; i < 8; i++) {
        int d0 = i * 128 + lane * 4;
        float4 xv = *(const float4*)(xr + d0);
        __half2 p0 = __floats2half2_rn(xv.x, xv.y);
        __half2 p1 = __floats2half2_rn(xv.z, xv.w);
        uint2 pk = make_uint2(*(uint32_t*)&p0, *(uint32_t*)&p1);
        *(uint2*)(g_xh + (size_t)t * DD + d0) = pk;

        float xa[4] = { xv.x, xv.y, xv.z, xv.w };
#pragma unroll
        for (int j = 0; j < 4; j++) {
            const float4* wp = (const float4*)(s_wr + (size_t)(d0 + j) * EE);
            float4 w0 = wp[0], w1 = wp[1];
            acc[0] += xa[j] * w0.x;  acc[1] += xa[j] * w0.y;
            acc[2] += xa[j] * w0.z;  acc[3] += xa[j] * w0.w;
            acc[4] += xa[j] * w1.x;  acc[5] += xa[j] * w1.y;
            acc[6] += xa[j] * w1.z;  acc[7] += xa[j] * w1.w;
        }
    }
#pragma unroll
    for (int off = 16; off > 0; off >>= 1)
#pragma unroll
        for (int e = 0; e < EE; e++)
            acc[e] += __shfl_xor_sync(0xffffffffu, acc[e], off);

    if (lane == 0) {
        float m = acc[0];
#pragma unroll
        for (int e = 1; e < EE; e++) m = fmaxf(m, acc[e]);
        float p[EE], s = 0.f;
#pragma unroll
        for (int e = 0; e < EE; e++) { p[e] = expf(acc[e] - m); s += p[e]; }
        float inv = 1.f / s;
#pragma unroll
        for (int e = 0; e < EE; e++) p[e] *= inv;

        int be = 0; float b = p[0];
#pragma unroll
        for (int e = 1; e < EE; e++) if (p[e] > b) { b = p[e]; be = e; }
        int be2 = -1; float b2 = -1.f;
#pragma unroll
        for (int e = 0; e < EE; e++)
            if (e != be && p[e] > b2) { b2 = p[e]; be2 = e; }

        float w0 = 1.f / (1.f + expf(b2 - b));
        float w1 = 1.f - w0;

        g_eidx[2*t]   = be;   g_ew[2*t]   = w0;
        g_eidx[2*t+1] = be2;  g_ew[2*t+1] = w1;
        atomicAdd(&g_counts[be], 1);
        atomicAdd(&g_counts[be2], 1);
    }
}

// ---------------- offsets + scatter fused ----------------
__global__ void offsets_scatter_kernel() {
    if (blockIdx.x == 0 && threadIdx.x == 0) {
        int off = 0;
#pragma unroll
        for (int e = 0; e < EE; e++) {
            g_offsets[e] = off;
            off += (g_counts[e] + 127) & ~127;
        }
        g_offsets[EE] = off;
        __threadfence();
        atomicExch(&g_flag, 1);
    }
    if (threadIdx.x == 0) {
        while (atomicAdd(&g_flag, 0) == 0) __nanosleep(64);
    }
    __syncthreads();

    int i = blockIdx.x * blockDim.x + threadIdx.x;
    if (i >= NASG) return;
    int e = g_eidx[i];
    int pos = atomicAdd(&g_cursor[e], 1);
    int a = g_offsets[e] + pos;
    g_token_of[a] = i >> 1;
    g_weight_of[a] = g_ew[i];
}

// ======================= ff1 : gate+up grouped GEMM (fp16 mma) ===============
// BM=128, BN=64 (two Bs), BK=64, 3 stages, 256 threads, warp tile 32x32(x2).
// A: 128 rows x 144B (128 data + 16 pad) = 18432. Bg/Bu: 64 rows x 144B = 9216 each.
#define F1_STAGE 36864
#define F1_BG    18432
#define F1_BU    27648

__global__ void __launch_bounds__(256, 2)
ff1_tc(const __half* __restrict__ xh,
       const __half* __restrict__ wgh,
       const __half* __restrict__ wuh) {
    extern __shared__ char smem[];
    int m0 = blockIdx.y * 128;
    if (m0 >= g_offsets[EE]) return;
    int e = 0;
#pragma unroll
    for (int i = 0; i < EE; i++) if (m0 >= g_offsets[i+1]) e = i + 1;
    int n0 = blockIdx.x * 64;

    int tid = threadIdx.x, wid = tid >> 5, lane = tid & 31;
    int wm = wid & 3, wn = wid >> 2;
    int ly = lane >> 2, lx = lane & 3;
    uint32_t sb = s2u(smem);

    // A loader: 2 threads/row, 4 chunks each (row = 128B data)
    int ar = tid >> 1, ah = tid & 1;
    int tok = g_token_of[m0 + ar]; if (tok < 0) tok = 0;
    const char* aSrc = (const char*)(xh + (size_t)tok * DD) + ah * 64;
    uint32_t aDst = (uint32_t)(ar * 144 + ah * 64);
    // B loader: rows brow and brow+32 for both g and u
    const char* gBase = (const char*)(wgh + ((size_t)e << 20) + n0);
    const char* uBase = (const char*)(wuh + ((size_t)e << 20) + n0);
    int brow = tid >> 3, bcol = (tid & 7) * 16;     // brow 0..31

    float accG[2][4][4], accU[2][4][4];
#pragma unroll
    for (int a = 0; a < 2; a++)
#pragma unroll
        for (int b = 0; b < 4; b++)
#pragma unroll
            for (int c = 0; c < 4; c++) { accG[a][b][c] = 0.f; accU[a][b][c] = 0.f; }

#define F1_LOAD(kt, slot) do { \
    uint32_t s_ = sb + (slot) * F1_STAGE; \
    const char* as_ = aSrc + (kt) * 128; \
    CP16(s_ + aDst,      as_);      CP16(s_ + aDst + 16, as_ + 16); \
    CP16(s_ + aDst + 32, as_ + 32); CP16(s_ + aDst + 48, as_ + 48); \
    size_t go_ = (size_t)((kt) * 64 + brow) * 2048 + bcol; \
    uint32_t bd_ = (uint32_t)(brow * 144 + bcol); \
    CP16(s_ + F1_BG + bd_,            gBase + go_); \
    CP16(s_ + F1_BU + bd_,            uBase + go_); \
    CP16(s_ + F1_BG + bd_ + 32*144,   gBase + go_ + (size_t)32*2048); \
    CP16(s_ + F1_BU + bd_ + 32*144,   uBase + go_ + (size_t)32*2048); \
    CP_COMMIT(); \
} while (0)

    F1_LOAD(0, 0);
    F1_LOAD(1, 1);

    uint32_t l16 = (uint32_t)(lane & 15), lh = (uint32_t)(lane >> 4) * 16;

    const int NIT = DD / 64;   // 16
#pragma unroll 1
    for (int kt = 0; kt < NIT; kt++) {
        if (kt == NIT - 1) { CP_WAIT(0); } else { CP_WAIT(1); }
        __syncthreads();
        if (kt + 2 < NIT) F1_LOAD(kt + 2, (kt + 2) % 3);

        uint32_t stg = sb + (kt % 3) * F1_STAGE;
#pragma unroll
        for (int ks = 0; ks < 4; ks++) {
            uint32_t a_fr[2][4];
#pragma unroll
            for (int mt = 0; mt < 2; mt++) {
                uint32_t aa = stg + (wm * 32 + mt * 16 + l16) * 144 + ks * 32 + lh;
                LDSM4(a_fr[mt][0], a_fr[mt][1], a_fr[mt][2], a_fr[mt][3], aa);
            }
#pragma unroll
            for (int nt = 0; nt < 2; nt++) {
                uint32_t bg = stg + F1_BG + (ks * 16 + l16) * 144 +
                              (wn * 32 + nt * 16) * 2 + lh;
                uint32_t g0, g1, g2, g3, u0, u1, u2, u3;
                LDSM4T(g0, g1, g2, g3, bg);
                LDSM4T(u0, u1, u2, u3, bg + (F1_BU - F1_BG));
#pragma unroll
                for (int mt = 0; mt < 2; mt++) {
                    MMA_F16(accG[mt][nt*2],   a_fr[mt], g0, g1);
                    MMA_F16(accG[mt][nt*2+1], a_fr[mt], g2, g3);
                    MMA_F16(accU[mt][nt*2],   a_fr[mt], u0, u1);
                    MMA_F16(accU[mt][nt*2+1], a_fr[mt], u2, u3);
                }
            }
        }
    }

    // epilogue: h = w * silu(g) * u -> fp16
#pragma unroll
    for (int mt = 0; mt < 2; mt++) {
        int r0 = m0 + wm * 32 + mt * 16 + ly;
        float w0 = g_weight_of[r0], w1 = g_weight_of[r0 + 8];
#pragma unroll
        for (int nt = 0; nt < 4; nt++) {
            int c = n0 + wn * 32 + nt * 8 + 2 * lx;
            float* G = accG[mt][nt];
            float* U = accU[mt][nt];
            float h0 = w0 * (G[0] / (1.f + __expf(-G[0]))) * U[0];
            float h1 = w0 * (G[1] / (1.f + __expf(-G[1]))) * U[1];
            float h2 = w1 * (G[2] / (1.f + __expf(-G[2]))) * U[2];
            float h3 = w1 * (G[3] / (1.f + __expf(-G[3]))) * U[3];
            *(__half2*)(g_h + (size_t)r0 * FF + c)       = __floats2half2_rn(h0, h1);
            *(__half2*)(g_h + (size_t)(r0 + 8) * FF + c) = __floats2half2_rn(h2, h3);
        }
    }
}

// ======================= ff2 : down grouped GEMM (fp16 mma) ==================
// BM=128, BN=128, BK=64, 3 stages, warp tile 32x64.
// A: 18432. B: 64 rows x 272B (256 data + 16 pad) = 17408. Stage = 35840.
#define F2_STAGE 35840
#define F2_B     18432

__global__ void __launch_bounds__(256, 2)
ff2_tc(const __half* __restrict__ wdh, float* __restrict__ out) {
    extern __shared__ char smem[];
    int m0 = blockIdx.y * 128;
    if (m0 >= g_offsets[EE]) return;
    int e = 0;
#pragma unroll
    for (int i = 0; i < EE; i++) if (m0 >= g_offsets[i+1]) e = i + 1;
    int n0 = blockIdx.x * 128;

    int tid = threadIdx.x, wid = tid >> 5, lane = tid & 31;
    int wm = wid & 3, wn = wid >> 2;
    int ly = lane >> 2, lx = lane & 3;
    uint32_t sb = s2u(smem);

    int ar = tid >> 1, ah = tid & 1;
    const char* aSrc = (const char*)(g_h + (size_t)(m0 + ar) * FF) + ah * 64;
    uint32_t aDst = (uint32_t)(ar * 144 + ah * 64);
    const char* bBase = (const char*)(wdh + ((size_t)e << 20) + n0);
    int brow = tid >> 4, bcol = (tid & 15) * 16;    // brow 0..15

    float acc[2][8][4];
#pragma unroll
    for (int a = 0; a < 2; a++)
#pragma unroll
        for (int b = 0; b < 8; b++)
#pragma unroll
            for (int c = 0; c < 4; c++) acc[a][b][c] = 0.f;

#define F2_LOAD(kt, slot) do { \
    uint32_t s_ = sb + (slot) * F2_STAGE; \
    const char* as_ = aSrc + (kt) * 128; \
    CP16(s_ + aDst,      as_);      CP16(s_ + aDst + 16, as_ + 16); \
    CP16(s_ + aDst + 32, as_ + 32); CP16(s_ + aDst + 48, as_ + 48); \
    _Pragma("unroll") \
    for (int q_ = 0; q_ < 4; q_++) { \
        int r_ = brow + q_ * 16; \
        CP16(s_ + F2_B + r_ * 272 + bcol, \
             bBase + (size_t)((kt) * 64 + r_) * 2048 + bcol); \
    } \
    CP_COMMIT(); \
} while (0)

    F2_LOAD(0, 0);
    F2_LOAD(1, 1);

    uint32_t l16 = (uint32_t)(lane & 15), lh = (uint32_t)(lane >> 4) * 16;

    const int NIT = FF / 64;   // 16
#pragma unroll 1
    for (int kt = 0; kt < NIT; kt++) {
        if (kt == NIT - 1) { CP_WAIT(0); } else { CP_WAIT(1); }
        __syncthreads();
        if (kt + 2 < NIT) F2_LOAD(kt + 2, (kt + 2) % 3);

        uint32_t stg = sb + (kt % 3) * F2_STAGE;
#pragma unroll
        for (int ks = 0; ks < 4; ks++) {
            uint32_t a_fr[2][4];
#pragma unroll
            for (int mt = 0; mt < 2; mt++) {
                uint32_t aa = stg + (wm * 32 + mt * 16 + l16) * 144 + ks * 32 + lh;
                LDSM4(a_fr[mt][0], a_fr[mt][1], a_fr[mt][2], a_fr[mt][3], aa);
            }
#pragma unroll
            for (int nt = 0; nt < 4; nt++) {
                uint32_t ba = stg + F2_B + (ks * 16 + l16) * 272 +
                              (wn * 64 + nt * 16) * 2 + lh;
                uint32_t b0, b1, b2, b3;
                LDSM4T(b0, b1, b2, b3, ba);
#pragma unroll
                for (int mt = 0; mt < 2; mt++) {
                    MMA_F16(acc[mt][nt*2],   a_fr[mt], b0, b1);
                    MMA_F16(acc[mt][nt*2+1], a_fr[mt], b2, b3);
                }
            }
        }
    }

    // RED epilogue: out[token] += y
#pragma unroll
    for (int mt = 0; mt < 2; mt++) {
        int r0 = m0 + wm * 32 + mt * 16 + ly;
        int t0 = g_token_of[r0], t1 = g_token_of[r0 + 8];
        float* o0 = out + (size_t)(t0 < 0 ? 0 : t0) * DD;
        float* o1 = out + (size_t)(t1 < 0 ? 0 : t1) * DD;
#pragma unroll
        for (int nt = 0; nt < 8; nt++) {
            int c = n0 + wn * 64 + nt * 8 + 2 * lx;
            float* A = acc[mt][nt];
            if (t0 >= 0) { atomicAdd(o0 + c, A[0]); atomicAdd(o0 + c + 1, A[1]); }
            if (t1 >= 0) { atomicAdd(o1 + c, A[2]); atomicAdd(o1 + c + 1, A[3]); }
        }
    }
}

// ---------------- launch ----------------
extern "C" void kernel_launch(void* const* d_in, const int* in_sizes, int n_in,
                              void* d_out, int out_size) {
    const float* x  = (const float*)d_in[0];
    const float* wr = (const float*)d_in[1];
    const float* wg = (const float*)d_in[2];
    const float* wu = (const float*)d_in[3];
    const float* wd = (const float*)d_in[4];
    float* out = (float*)d_out;

    cudaFuncSetAttribute(ff1_tc, cudaFuncAttributeMaxDynamicSharedMemorySize, 3 * F1_STAGE);
    cudaFuncSetAttribute(ff2_tc, cudaFuncAttributeMaxDynamicSharedMemorySize, 3 * F2_STAGE);

    prep_kernel<<<(8 * (1 << 20)) / 256, 256>>>(out, wg, wu, wd);
    router_kernel<<<NTOK / 8, 256>>>(x, wr);
    offsets_scatter_kernel<<<NASG / 256, 256>>>();

    __half* xh_p;  cudaGetSymbolAddress((void**)&xh_p,  g_xh);
    __half* wgh_p; cudaGetSymbolAddress((void**)&wgh_p, g_wgh);
    __half* wuh_p; cudaGetSymbolAddress((void**)&wuh_p, g_wuh);
    __half* wdh_p; cudaGetSymbolAddress((void**)&wdh_p, g_wdh);

    {
        dim3 g(FF / 64, MTILES);
        ff1_tc<<<g, 256, 3 * F1_STAGE>>>(xh_p, wgh_p, wuh_p);
    }
    {
        dim3 g(DD / 128, MTILES);
        ff2_tc<<<g, 256, 3 * F2_STAGE>>>(wdh_p, out);
    }
}

// round 11
// speedup vs baseline: 1.0310x; 1.0310x over previous
#include <cuda_runtime.h>
#include <cuda_fp16.h>
#include <math.h>
#include <stdint.h>

#define BB 4
#define TT 2048
#define DD 1024
#define EE 8
#define FF 1024
#define NTOK (BB*TT)           // 8192
#define NASG (NTOK*2)          // 16384
#define MAXA (NASG + EE*128)   // 17408
#define MTILES (MAXA/128)      // 136

// ---------------- scratch ----------------
__device__ int   g_counts[EE];
__device__ int   g_cursor[EE];
__device__ int   g_offsets[EE+1];
__device__ int   g_eidx[NASG];
__device__ float g_ew[NASG];
__device__ int   g_token_of[MAXA];
__device__ float g_weight_of[MAXA];
__device__ int   g_flag;

__device__ __half g_xh [(size_t)NTOK*DD];
__device__ __half g_wgh[(size_t)EE*DD*FF];
__device__ __half g_wuh[(size_t)EE*DD*FF];
__device__ __half g_wdh[(size_t)EE*FF*DD];
__device__ __half g_h  [(size_t)MAXA*FF];

// ---------------- PTX helpers ----------------
__device__ __forceinline__ uint32_t s2u(const void* p) {
    uint32_t a;
    asm("{ .reg .u64 t; cvta.to.shared.u64 t, %1; cvt.u32.u64 %0, t; }" : "=r"(a) : "l"(p));
    return a;
}
#define CP16(dst, src) \
    asm volatile("cp.async.cg.shared.global [%0], [%1], 16;" :: "r"(dst), "l"(src) : "memory")
#define CP_COMMIT() asm volatile("cp.async.commit_group;" ::: "memory")
#define CP_WAIT(N)  asm volatile("cp.async.wait_group %0;" :: "n"(N) : "memory")

#define LDSM4(r0, r1, r2, r3, a) \
    asm volatile("ldmatrix.sync.aligned.m8n8.x4.shared.b16 {%0,%1,%2,%3}, [%4];" \
        : "=r"(r0), "=r"(r1), "=r"(r2), "=r"(r3) : "r"(a))
#define LDSM4T(r0, r1, r2, r3, a) \
    asm volatile("ldmatrix.sync.aligned.m8n8.x4.trans.shared.b16 {%0,%1,%2,%3}, [%4];" \
        : "=r"(r0), "=r"(r1), "=r"(r2), "=r"(r3) : "r"(a))

// mma m16n8k16 fp16 in, fp32 acc
#define MMA_F16(d, a, b0, b1) \
    asm volatile("mma.sync.aligned.m16n8k16.row.col.f32.f16.f16.f32 " \
        "{%0,%1,%2,%3}, {%4,%5,%6,%7}, {%8,%9}, {%0,%1,%2,%3};" \
        : "+f"((d)[0]), "+f"((d)[1]), "+f"((d)[2]), "+f"((d)[3]) \
        : "r"((a)[0]), "r"((a)[1]), "r"((a)[2]), "r"((a)[3]), \
          "r"(b0), "r"(b1))

// ---------------- prep: zero out + counters + weight fp16 convert ----------
__global__ void prep_kernel(float* __restrict__ out,
                            const float* __restrict__ wg,
                            const float* __restrict__ wu,
                            const float* __restrict__ wd) {
    int idx = blockIdx.x * blockDim.x + threadIdx.x;     // 0 .. 8M-1
    if (idx < EE) { g_counts[idx] = 0; g_cursor[idx] = 0; }
    if (idx == 0) g_flag = 0;
    if (idx < MAXA) { g_token_of[idx] = -1; g_weight_of[idx] = 0.f; }

    const int OUT4 = NTOK * DD / 4;                      // 2M
    if (idx < OUT4) {
        ((float4*)out)[idx] = make_float4(0.f, 0.f, 0.f, 0.f);
    } else {
        int j = idx - OUT4;                              // 0 .. 6M-1
        int region = j >> 21;
        int off = j & ((1 << 21) - 1);
        const float* src;
        __half* dst;
        switch (region) {
            case 0:  src = wg; dst = g_wgh; break;
            case 1:  src = wu; dst = g_wuh; break;
            default: src = wd; dst = g_wdh; break;
        }
        float4 v = ((const float4*)src)[off];
        __half2 a = __floats2half2_rn(v.x, v.y);
        __half2 b = __floats2half2_rn(v.z, v.w);
        ((__half2*)dst)[2*off]   = a;
        ((__half2*)dst)[2*off+1] = b;
    }
}

// ---------------- router (also emits fp16 x) ----------------
__global__ void router_kernel(const float* __restrict__ x,
                              const float* __restrict__ wr) {
    __shared__ float s_wr[DD * EE];
    int tid = threadIdx.x;
    for (int i = tid; i < DD * EE / 4; i += blockDim.x)
        ((float4*)s_wr)[i] = ((const float4*)wr)[i];
    __syncthreads();

    int warp = tid >> 5, lane = tid & 31;
    int t = blockIdx.x * 8 + warp;
    const float* xr = x + (size_t)t * DD;

    float acc[EE];
#pragma unroll
    for (int e = 0; e < EE; e++) acc[e] = 0.f;
#pragma unroll
    for (int i = 0; i < 8; i++) {
        int d0 = i * 128 + lane * 4;
        float4 xv = *(const float4*)(xr + d0);
        __half2 p0 = __floats2half2_rn(xv.x, xv.y);
        __half2 p1 = __floats2half2_rn(xv.z, xv.w);
        uint2 pk = make_uint2(*(uint32_t*)&p0, *(uint32_t*)&p1);
        *(uint2*)(g_xh + (size_t)t * DD + d0) = pk;

        float xa[4] = { xv.x, xv.y, xv.z, xv.w };
#pragma unroll
        for (int j = 0; j < 4; j++) {
            const float4* wp = (const float4*)(s_wr + (size_t)(d0 + j) * EE);
            float4 w0 = wp[0], w1 = wp[1];
            acc[0] += xa[j] * w0.x;  acc[1] += xa[j] * w0.y;
            acc[2] += xa[j] * w0.z;  acc[3] += xa[j] * w0.w;
            acc[4] += xa[j] * w1.x;  acc[5] += xa[j] * w1.y;
            acc[6] += xa[j] * w1.z;  acc[7] += xa[j] * w1.w;
        }
    }
#pragma unroll
    for (int off = 16; off > 0; off >>= 1)
#pragma unroll
        for (int e = 0; e < EE; e++)
            acc[e] += __shfl_xor_sync(0xffffffffu, acc[e], off);

    if (lane == 0) {
        float m = acc[0];
#pragma unroll
        for (int e = 1; e < EE; e++) m = fmaxf(m, acc[e]);
        float p[EE], s = 0.f;
#pragma unroll
        for (int e = 0; e < EE; e++) { p[e] = expf(acc[e] - m); s += p[e]; }
        float inv = 1.f / s;
#pragma unroll
        for (int e = 0; e < EE; e++) p[e] *= inv;

        int be = 0; float b = p[0];
#pragma unroll
        for (int e = 1; e < EE; e++) if (p[e] > b) { b = p[e]; be = e; }
        int be2 = -1; float b2 = -1.f;
#pragma unroll
        for (int e = 0; e < EE; e++)
            if (e != be && p[e] > b2) { b2 = p[e]; be2 = e; }

        float w0 = 1.f / (1.f + expf(b2 - b));
        float w1 = 1.f - w0;

        g_eidx[2*t]   = be;   g_ew[2*t]   = w0;
        g_eidx[2*t+1] = be2;  g_ew[2*t+1] = w1;
        atomicAdd(&g_counts[be], 1);
        atomicAdd(&g_counts[be2], 1);
    }
}

// ---------------- offsets + scatter fused ----------------
__global__ void offsets_scatter_kernel() {
    if (blockIdx.x == 0 && threadIdx.x == 0) {
        int off = 0;
#pragma unroll
        for (int e = 0; e < EE; e++) {
            g_offsets[e] = off;
            off += (g_counts[e] + 127) & ~127;
        }
        g_offsets[EE] = off;
        __threadfence();
        atomicExch(&g_flag, 1);
    }
    if (threadIdx.x == 0) {
        while (atomicAdd(&g_flag, 0) == 0) __nanosleep(64);
    }
    __syncthreads();

    int i = blockIdx.x * blockDim.x + threadIdx.x;
    if (i >= NASG) return;
    int e = g_eidx[i];
    int pos = atomicAdd(&g_cursor[e], 1);
    int a = g_offsets[e] + pos;
    g_token_of[a] = i >> 1;
    g_weight_of[a] = g_ew[i];
}

// ======================= ff1 : gate+up grouped GEMM (fp16 mma) ===============
// BM=128, BN=64 (two Bs), BK=32, 4 stages, 256 threads, warp tile 32x32.
// Cross-barrier fragment prefetch; tail waits drain fully (fixes R10 race).
#define F1_STAGE 19456
#define F1_BOFF  10240

__global__ void __launch_bounds__(256, 2)
ff1_tc(const __half* __restrict__ xh,
       const __half* __restrict__ wgh,
       const __half* __restrict__ wuh) {
    extern __shared__ char smem[];
    int m0 = blockIdx.y * 128;
    if (m0 >= g_offsets[EE]) return;
    int e = 0;
#pragma unroll
    for (int i = 0; i < EE; i++) if (m0 >= g_offsets[i+1]) e = i + 1;
    int n0 = blockIdx.x * 64;

    int tid = threadIdx.x, wid = tid >> 5, lane = tid & 31;
    int wm = wid & 3, wn = wid >> 2;
    int ly = lane >> 2, lx = lane & 3;
    uint32_t sb = s2u(smem);

    int ar = tid >> 1, ah = tid & 1;
    int tok = g_token_of[m0 + ar]; if (tok < 0) tok = 0;
    const char* aSrc = (const char*)(xh + (size_t)tok * DD) + ah * 32;
    uint32_t aDst = (uint32_t)(ar * 80 + ah * 32);
    const char* gBase = (const char*)(wgh + ((size_t)e << 20) + n0);
    const char* uBase = (const char*)(wuh + ((size_t)e << 20) + n0);
    int id0 = tid, id1 = tid + 256;
    int brow0 = id0 >> 3, bc0 = (id0 & 7) * 16;
    int brow1 = id1 >> 3, bc1 = (id1 & 7) * 16;
    int bmat0 = brow0 >> 5, bk0 = brow0 & 31;
    int bmat1 = brow1 >> 5, bk1 = brow1 & 31;
    const char* bsrc0 = (bmat0 ? uBase : gBase) + bc0;
    const char* bsrc1 = (bmat1 ? uBase : gBase) + bc1;
    uint32_t bdst0 = (uint32_t)(F1_BOFF + bmat0 * 4608 + bk0 * 144 + bc0);
    uint32_t bdst1 = (uint32_t)(F1_BOFF + bmat1 * 4608 + bk1 * 144 + bc1);

    float accG[2][4][4], accU[2][4][4];
#pragma unroll
    for (int a = 0; a < 2; a++)
#pragma unroll
        for (int b = 0; b < 4; b++)
#pragma unroll
            for (int c = 0; c < 4; c++) { accG[a][b][c] = 0.f; accU[a][b][c] = 0.f; }

#define F1_LOAD(kt, slot) do { \
    uint32_t s_ = sb + (slot) * F1_STAGE; \
    const char* as_ = aSrc + (kt) * 64; \
    CP16(s_ + aDst, as_);  CP16(s_ + aDst + 16, as_ + 16); \
    CP16(s_ + bdst0, bsrc0 + (size_t)((kt) * 32 + bk0) * 2048); \
    CP16(s_ + bdst1, bsrc1 + (size_t)((kt) * 32 + bk1) * 2048); \
    CP_COMMIT(); \
} while (0)

    F1_LOAD(0, 0);
    F1_LOAD(1, 1);
    F1_LOAD(2, 2);

    uint32_t l16 = (uint32_t)(lane & 15), lh = (uint32_t)(lane >> 4) * 16;

    // prefetched fragments for (kt, ks=0): A mt0/mt1 + B nt0 (g,u)
    uint32_t pa0[4], pa1[4], pg[4], pu[4];

#define F1_PREFETCH(stg_) do { \
    LDSM4(pa0[0], pa0[1], pa0[2], pa0[3], (stg_) + (wm * 32 + l16) * 80 + lh); \
    LDSM4(pa1[0], pa1[1], pa1[2], pa1[3], (stg_) + (wm * 32 + 16 + l16) * 80 + lh); \
    uint32_t bg_ = (stg_) + F1_BOFF + l16 * 144 + (wn * 32) * 2 + lh; \
    LDSM4T(pg[0], pg[1], pg[2], pg[3], bg_); \
    LDSM4T(pu[0], pu[1], pu[2], pu[3], bg_ + 4608); \
} while (0)

    CP_WAIT(2);
    __syncthreads();
    F1_PREFETCH(sb);

    const int NIT = DD / 32;
#pragma unroll 1
    for (int kt = 0; kt < NIT; kt++) {
        // need slot kt (body) AND slot kt+1 (end-of-body prefetch) complete.
        // groups committed through kt+2 here; last two iterations must drain fully.
        if (kt < NIT - 2) { CP_WAIT(1); } else { CP_WAIT(0); }
        __syncthreads();
        if (kt + 3 < NIT) F1_LOAD(kt + 3, (kt + 3) & 3);
        uint32_t stg = sb + (kt & 3) * F1_STAGE;

        // ks=0, nt=0 : fragments already in registers -> immediate HMMA burst
        MMA_F16(accG[0][0], pa0, pg[0], pg[1]);
        MMA_F16(accG[0][1], pa0, pg[2], pg[3]);
        MMA_F16(accU[0][0], pa0, pu[0], pu[1]);
        MMA_F16(accU[0][1], pa0, pu[2], pu[3]);
        MMA_F16(accG[1][0], pa1, pg[0], pg[1]);
        MMA_F16(accG[1][1], pa1, pg[2], pg[3]);
        MMA_F16(accU[1][0], pa1, pu[0], pu[1]);
        MMA_F16(accU[1][1], pa1, pu[2], pu[3]);

        // ks=0, nt=1
        {
            uint32_t bg = stg + F1_BOFF + l16 * 144 + (wn * 32 + 16) * 2 + lh;
            uint32_t g0, g1, g2, g3, u0, u1, u2, u3;
            LDSM4T(g0, g1, g2, g3, bg);
            LDSM4T(u0, u1, u2, u3, bg + 4608);
            MMA_F16(accG[0][2], pa0, g0, g1);
            MMA_F16(accG[0][3], pa0, g2, g3);
            MMA_F16(accU[0][2], pa0, u0, u1);
            MMA_F16(accU[0][3], pa0, u2, u3);
            MMA_F16(accG[1][2], pa1, g0, g1);
            MMA_F16(accG[1][3], pa1, g2, g3);
            MMA_F16(accU[1][2], pa1, u0, u1);
            MMA_F16(accU[1][3], pa1, u2, u3);
        }

        // ks=1 (full fragment loads)
        {
            uint32_t a0[4], a1[4];
            LDSM4(a0[0], a0[1], a0[2], a0[3], stg + (wm * 32 + l16) * 80 + 32 + lh);
            LDSM4(a1[0], a1[1], a1[2], a1[3], stg + (wm * 32 + 16 + l16) * 80 + 32 + lh);
#pragma unroll
            for (int nt = 0; nt < 2; nt++) {
                uint32_t bg = stg + F1_BOFF + (16 + l16) * 144 + (wn * 32 + nt * 16) * 2 + lh;
                uint32_t g0, g1, g2, g3, u0, u1, u2, u3;
                LDSM4T(g0, g1, g2, g3, bg);
                LDSM4T(u0, u1, u2, u3, bg + 4608);
                MMA_F16(accG[0][nt*2],   a0, g0, g1);
                MMA_F16(accG[0][nt*2+1], a0, g2, g3);
                MMA_F16(accU[0][nt*2],   a0, u0, u1);
                MMA_F16(accU[0][nt*2+1], a0, u2, u3);
                MMA_F16(accG[1][nt*2],   a1, g0, g1);
                MMA_F16(accG[1][nt*2+1], a1, g2, g3);
                MMA_F16(accU[1][nt*2],   a1, u0, u1);
                MMA_F16(accU[1][nt*2+1], a1, u2, u3);
            }
        }

        // prefetch next iteration's ks=0 fragments (slot kt+1 visible by wait+sync)
        if (kt + 1 < NIT) F1_PREFETCH(sb + ((kt + 1) & 3) * F1_STAGE);
    }

    // epilogue: h = w * silu(g) * u -> fp16
#pragma unroll
    for (int mt = 0; mt < 2; mt++) {
        int r0 = m0 + wm * 32 + mt * 16 + ly;
        float w0 = g_weight_of[r0], w1 = g_weight_of[r0 + 8];
#pragma unroll
        for (int nt = 0; nt < 4; nt++) {
            int c = n0 + wn * 32 + nt * 8 + 2 * lx;
            float* G = accG[mt][nt];
            float* U = accU[mt][nt];
            float h0 = w0 * (G[0] / (1.f + __expf(-G[0]))) * U[0];
            float h1 = w0 * (G[1] / (1.f + __expf(-G[1]))) * U[1];
            float h2 = w1 * (G[2] / (1.f + __expf(-G[2]))) * U[2];
            float h3 = w1 * (G[3] / (1.f + __expf(-G[3]))) * U[3];
            *(__half2*)(g_h + (size_t)r0 * FF + c)       = __floats2half2_rn(h0, h1);
            *(__half2*)(g_h + (size_t)(r0 + 8) * FF + c) = __floats2half2_rn(h2, h3);
        }
    }
}

// ======================= ff2 : down grouped GEMM (fp16 mma) ==================
// BM=128, BN=128, BK=32, 4 stages, warp tile 32x64. RED epilogue into out.
#define F2_STAGE 18944
#define F2_BOFF  10240

__global__ void __launch_bounds__(256, 2)
ff2_tc(const __half* __restrict__ wdh, float* __restrict__ out) {
    extern __shared__ char smem[];
    int m0 = blockIdx.y * 128;
    if (m0 >= g_offsets[EE]) return;
    int e = 0;
#pragma unroll
    for (int i = 0; i < EE; i++) if (m0 >= g_offsets[i+1]) e = i + 1;
    int n0 = blockIdx.x * 128;

    int tid = threadIdx.x, wid = tid >> 5, lane = tid & 31;
    int wm = wid & 3, wn = wid >> 2;
    int ly = lane >> 2, lx = lane & 3;
    uint32_t sb = s2u(smem);

    int ar = tid >> 1, ah = tid & 1;
    const char* aSrc = (const char*)(g_h + (size_t)(m0 + ar) * FF) + ah * 32;
    uint32_t aDst = (uint32_t)(ar * 80 + ah * 32);
    const char* bBase = (const char*)(wdh + ((size_t)e << 20) + n0);
    int id0 = tid, id1 = tid + 256;
    int bk0 = id0 >> 4, bc0 = (id0 & 15) * 16;
    int bk1 = id1 >> 4, bc1 = (id1 & 15) * 16;
    uint32_t bdst0 = (uint32_t)(F2_BOFF + bk0 * 272 + bc0);
    uint32_t bdst1 = (uint32_t)(F2_BOFF + bk1 * 272 + bc1);

    float acc[2][8][4];
#pragma unroll
    for (int a = 0; a < 2; a++)
#pragma unroll
        for (int b = 0; b < 8; b++)
#pragma unroll
            for (int c = 0; c < 4; c++) acc[a][b][c] = 0.f;

#define F2_LOAD(kt, slot) do { \
    uint32_t s_ = sb + (slot) * F2_STAGE; \
    const char* as_ = aSrc + (kt) * 64; \
    CP16(s_ + aDst, as_);  CP16(s_ + aDst + 16, as_ + 16); \
    CP16(s_ + bdst0, bBase + (size_t)((kt) * 32 + bk0) * 2048 + bc0); \
    CP16(s_ + bdst1, bBase + (size_t)((kt) * 32 + bk1) * 2048 + bc1); \
    CP_COMMIT(); \
} while (0)

    F2_LOAD(0, 0);
    F2_LOAD(1, 1);
    F2_LOAD(2, 2);

    uint32_t l16 = (uint32_t)(lane & 15), lh = (uint32_t)(lane >> 4) * 16;

    uint32_t pa0[4], pa1[4], pb[4];

#define F2_PREFETCH(stg_) do { \
    LDSM4(pa0[0], pa0[1], pa0[2], pa0[3], (stg_) + (wm * 32 + l16) * 80 + lh); \
    LDSM4(pa1[0], pa1[1], pa1[2], pa1[3], (stg_) + (wm * 32 + 16 + l16) * 80 + lh); \
    LDSM4T(pb[0], pb[1], pb[2], pb[3], (stg_) + F2_BOFF + l16 * 272 + (wn * 64) * 2 + lh); \
} while (0)

    CP_WAIT(2);
    __syncthreads();
    F2_PREFETCH(sb);

    const int NIT = FF / 32;
#pragma unroll 1
    for (int kt = 0; kt < NIT; kt++) {
        if (kt < NIT - 2) { CP_WAIT(1); } else { CP_WAIT(0); }
        __syncthreads();
        if (kt + 3 < NIT) F2_LOAD(kt + 3, (kt + 3) & 3);
        uint32_t stg = sb + (kt & 3) * F2_STAGE;

        // ks=0, nt=0 (prefetched)
        MMA_F16(acc[0][0], pa0, pb[0], pb[1]);
        MMA_F16(acc[0][1], pa0, pb[2], pb[3]);
        MMA_F16(acc[1][0], pa1, pb[0], pb[1]);
        MMA_F16(acc[1][1], pa1, pb[2], pb[3]);

        // ks=0, nt=1..3
#pragma unroll
        for (int nt = 1; nt < 4; nt++) {
            uint32_t ba = stg + F2_BOFF + l16 * 272 + (wn * 64 + nt * 16) * 2 + lh;
            uint32_t b0, b1, b2, b3;
            LDSM4T(b0, b1, b2, b3, ba);
            MMA_F16(acc[0][nt*2],   pa0, b0, b1);
            MMA_F16(acc[0][nt*2+1], pa0, b2, b3);
            MMA_F16(acc[1][nt*2],   pa1, b0, b1);
            MMA_F16(acc[1][nt*2+1], pa1, b2, b3);
        }

        // ks=1 (full)
        {
            uint32_t a0[4], a1[4];
            LDSM4(a0[0], a0[1], a0[2], a0[3], stg + (wm * 32 + l16) * 80 + 32 + lh);
            LDSM4(a1[0], a1[1], a1[2], a1[3], stg + (wm * 32 + 16 + l16) * 80 + 32 + lh);
#pragma unroll
            for (int nt = 0; nt < 4; nt++) {
                uint32_t ba = stg + F2_BOFF + (16 + l16) * 272 + (wn * 64 + nt * 16) * 2 + lh;
                uint32_t b0, b1, b2, b3;
                LDSM4T(b0, b1, b2, b3, ba);
                MMA_F16(acc[0][nt*2],   a0, b0, b1);
                MMA_F16(acc[0][nt*2+1], a0, b2, b3);
                MMA_F16(acc[1][nt*2],   a1, b0, b1);
                MMA_F16(acc[1][nt*2+1], a1, b2, b3);
            }
        }

        if (kt + 1 < NIT) F2_PREFETCH(sb + ((kt + 1) & 3) * F2_STAGE);
    }

    // RED epilogue: out[token] += y
#pragma unroll
    for (int mt = 0; mt < 2; mt++) {
        int r0 = m0 + wm * 32 + mt * 16 + ly;
        int t0 = g_token_of[r0], t1 = g_token_of[r0 + 8];
        float* o0 = out + (size_t)(t0 < 0 ? 0 : t0) * DD;
        float* o1 = out + (size_t)(t1 < 0 ? 0 : t1) * DD;
#pragma unroll
        for (int nt = 0; nt < 8; nt++) {
            int c = n0 + wn * 64 + nt * 8 + 2 * lx;
            float* A = acc[mt][nt];
            if (t0 >= 0) { atomicAdd(o0 + c, A[0]); atomicAdd(o0 + c + 1, A[1]); }
            if (t1 >= 0) { atomicAdd(o1 + c, A[2]); atomicAdd(o1 + c + 1, A[3]); }
        }
    }
}

// ---------------- launch ----------------
extern "C" void kernel_launch(void* const* d_in, const int* in_sizes, int n_in,
                              void* d_out, int out_size) {
    const float* x  = (const float*)d_in[0];
    const float* wr = (const float*)d_in[1];
    const float* wg = (const float*)d_in[2];
    const float* wu = (const float*)d_in[3];
    const float* wd = (const float*)d_in[4];
    float* out = (float*)d_out;

    cudaFuncSetAttribute(ff1_tc, cudaFuncAttributeMaxDynamicSharedMemorySize, 4 * F1_STAGE);
    cudaFuncSetAttribute(ff2_tc, cudaFuncAttributeMaxDynamicSharedMemorySize, 4 * F2_STAGE);

    prep_kernel<<<(8 * (1 << 20)) / 256, 256>>>(out, wg, wu, wd);
    router_kernel<<<NTOK / 8, 256>>>(x, wr);
    offsets_scatter_kernel<<<NASG / 256, 256>>>();

    __half* xh_p;  cudaGetSymbolAddress((void**)&xh_p,  g_xh);
    __half* wgh_p; cudaGetSymbolAddress((void**)&wgh_p, g_wgh);
    __half* wuh_p; cudaGetSymbolAddress((void**)&wuh_p, g_wuh);
    __half* wdh_p; cudaGetSymbolAddress((void**)&wdh_p, g_wdh);

    {
        dim3 g(FF / 64, MTILES);
        ff1_tc<<<g, 256, 4 * F1_STAGE>>>(xh_p, wgh_p, wuh_p);
    }
    {
        dim3 g(DD / 128, MTILES);
        ff2_tc<<<g, 256, 4 * F2_STAGE>>>(wdh_p, out);
    }
}